// round 3
// baseline (speedup 1.0000x reference)
#include <cuda_runtime.h>
#include <cstdint>

#define NN 100000
#define EE 1600000
#define DD 128

// Scratch (no allocation allowed):
__device__ float g_xw[(size_t)NN * DD];   // x @ W   (51.2 MB)
__device__ float g_deg[NN];
__device__ float g_dinv[NN];

// ---------------------------------------------------------------------------
// 1) degree init: self-loop contributes weight 1.0
__global__ void deg_init_kernel() {
    int i = blockIdx.x * blockDim.x + threadIdx.x;
    if (i < NN) g_deg[i] = 1.0f;
}

// 2) degree accumulation at targets (col)
__global__ void deg_accum_kernel(const int* __restrict__ ei,
                                 const float* __restrict__ ew) {
    int e = blockIdx.x * blockDim.x + threadIdx.x;
    if (e < EE) {
        int c = ei[EE + e];   // edge_index[1] = target
        atomicAdd(&g_deg[c], ew[e]);
    }
}

// 3) dinv = rsqrt(deg) (deg >= 1 always due to self-loop)
__global__ void dinv_kernel() {
    int i = blockIdx.x * blockDim.x + threadIdx.x;
    if (i < NN) {
        float d = g_deg[i];
        g_dinv[i] = (d > 0.0f) ? rsqrtf(d) : 0.0f;
    }
}

// ---------------------------------------------------------------------------
// 4) SGEMM: g_xw[N,128] = x[N,128] @ w[128,128]
//    Tile: 64 rows x 128 cols per block, 256 threads, 4x8 micro-tile/thread.
__global__ void __launch_bounds__(256) gemm_kernel(const float* __restrict__ x,
                                                   const float* __restrict__ w) {
    __shared__ float xs[64 * 132];                 // 132-float padded rows
    const int tid  = threadIdx.x;
    const int base = blockIdx.x * 64;

    // cooperative tile load: 64*128 floats = 2048 float4, 8 per thread
    const float4* xg  = (const float4*)x;
    float4*       xs4 = (float4*)xs;
#pragma unroll
    for (int i = 0; i < 8; i++) {
        int v = tid + i * 256;          // float4 index
        int r = v >> 5;                 // row within tile (32 float4 per row)
        int c = v & 31;
        float4 val = make_float4(0.f, 0.f, 0.f, 0.f);
        if (base + r < NN) val = xg[(size_t)(base + r) * 32 + c];
        xs4[r * 33 + c] = val;          // 33 float4 = 132-float row stride
    }
    __syncthreads();

    const int tcol = tid & 15;          // covers cols tcol*8 .. +7
    const int trow = tid >> 4;          // covers rows trow*4 .. +3

    float acc[4][8];
#pragma unroll
    for (int i = 0; i < 4; i++)
#pragma unroll
        for (int j = 0; j < 8; j++) acc[i][j] = 0.0f;

    const float4* w4 = (const float4*)w;
#pragma unroll 4
    for (int k = 0; k < 128; k++) {
        float4 w0 = __ldg(&w4[k * 32 + tcol * 2]);
        float4 w1 = __ldg(&w4[k * 32 + tcol * 2 + 1]);
        float wv[8] = {w0.x, w0.y, w0.z, w0.w, w1.x, w1.y, w1.z, w1.w};
#pragma unroll
        for (int i = 0; i < 4; i++) {
            float xv = xs[(trow * 4 + i) * 132 + k];
#pragma unroll
            for (int j = 0; j < 8; j++) acc[i][j] += xv * wv[j];
        }
    }

#pragma unroll
    for (int i = 0; i < 4; i++) {
        int r = base + trow * 4 + i;
        if (r < NN) {
            float4* o = (float4*)&g_xw[(size_t)r * 128 + tcol * 8];
            o[0] = make_float4(acc[i][0], acc[i][1], acc[i][2], acc[i][3]);
            o[1] = make_float4(acc[i][4], acc[i][5], acc[i][6], acc[i][7]);
        }
    }
}

// ---------------------------------------------------------------------------
// 5) out init with self-loop term: out[i] = dinv[i]^2 * xw[i]
__global__ void out_init_kernel(float* __restrict__ out) {
    int idx = blockIdx.x * blockDim.x + threadIdx.x;   // float4 index over N*32
    if (idx < NN * 32) {
        int r = idx >> 5;
        float s = g_dinv[r];
        s = s * s;
        float4 v = ((const float4*)g_xw)[idx];
        v.x *= s; v.y *= s; v.z *= s; v.w *= s;
        ((float4*)out)[idx] = v;
    }
}

// ---------------------------------------------------------------------------
// 6) edge scatter: warp per edge, vector REDG (red.global.add.v4.f32)
__global__ void __launch_bounds__(256) scatter_kernel(const int* __restrict__ ei,
                                                      const float* __restrict__ ew,
                                                      float* __restrict__ out) {
    int gw   = (blockIdx.x * blockDim.x + threadIdx.x) >> 5;  // edge id
    int lane = threadIdx.x & 31;
    if (gw >= EE) return;   // edge id is warp-uniform: whole warp exits together

    int row = 0, col = 0;
    float coef = 0.0f;
    if (lane == 0) {
        row  = ei[gw];          // source
        col  = ei[EE + gw];     // target
        coef = g_dinv[row] * ew[gw] * g_dinv[col];
    }
    row  = __shfl_sync(0xffffffffu, row, 0);
    col  = __shfl_sync(0xffffffffu, col, 0);
    coef = __shfl_sync(0xffffffffu, coef, 0);

    float4 v = ((const float4*)g_xw)[(size_t)row * 32 + lane];
    v.x *= coef; v.y *= coef; v.z *= coef; v.w *= coef;

    float* dst = out + (size_t)col * 128 + (size_t)lane * 4;
    asm volatile("red.global.add.v4.f32 [%0], {%1, %2, %3, %4};"
                 :: "l"(dst), "f"(v.x), "f"(v.y), "f"(v.z), "f"(v.w)
                 : "memory");
}

// ---------------------------------------------------------------------------
// 7) bias + PReLU
__global__ void prelu_kernel(float* __restrict__ out,
                             const float* __restrict__ bias,
                             const float* __restrict__ prelu_a) {
    int idx = blockIdx.x * blockDim.x + threadIdx.x;  // float4 index over N*32
    if (idx < NN * 32) {
        float a  = __ldg(prelu_a);
        float4 b = ((const float4*)bias)[idx & 31];
        float4 v = ((float4*)out)[idx];
        v.x += b.x; v.y += b.y; v.z += b.z; v.w += b.w;
        v.x = (v.x >= 0.f) ? v.x : a * v.x;
        v.y = (v.y >= 0.f) ? v.y : a * v.y;
        v.z = (v.z >= 0.f) ? v.z : a * v.z;
        v.w = (v.w >= 0.f) ? v.w : a * v.w;
        ((float4*)out)[idx] = v;
    }
}

// ---------------------------------------------------------------------------
extern "C" void kernel_launch(void* const* d_in, const int* in_sizes, int n_in,
                              void* d_out, int out_size) {
    const float* x    = (const float*)d_in[0];
    const int*   ei   = (const int*)d_in[1];     // JAX x64-disabled: int32!
    const float* ew   = (const float*)d_in[2];
    const float* w    = (const float*)d_in[3];
    const float* bias = (const float*)d_in[4];
    const float* pa   = (const float*)d_in[5];
    float*       out  = (float*)d_out;

    (void)in_sizes; (void)n_in; (void)out_size;

    // degree / dinv
    deg_init_kernel<<<(NN + 255) / 256, 256>>>();
    deg_accum_kernel<<<(EE + 255) / 256, 256>>>(ei, ew);
    dinv_kernel<<<(NN + 255) / 256, 256>>>();

    // xw = x @ W
    gemm_kernel<<<(NN + 63) / 64, 256>>>(x, w);

    // self-loop init
    out_init_kernel<<<(NN * 32 + 255) / 256, 256>>>(out);

    // edge aggregation (warp per edge)
    scatter_kernel<<<(int)(((size_t)EE * 32 + 255) / 256), 256>>>(ei, ew, out);

    // bias + PReLU
    prelu_kernel<<<(NN * 32 + 255) / 256, 256>>>(out, bias, pa);
}

// round 4
// speedup vs baseline: 1.6382x; 1.6382x over previous
#include <cuda_runtime.h>
#include <cstdint>

#define NN 100000
#define EE 1600000
#define DD 128

#define SCAN_THREADS 256
#define SCAN_PER_THREAD 8
#define SCAN_CHUNK (SCAN_THREADS * SCAN_PER_THREAD)   // 2048
#define SCAN_NB ((NN + SCAN_CHUNK - 1) / SCAN_CHUNK)  // 49

// Scratch (no device allocation allowed -> __device__ globals)
__device__ float g_xw[(size_t)NN * DD];   // x @ W (51.2 MB)
__device__ float g_deg[NN];
__device__ float g_dinv[NN];
__device__ int   g_cnt[NN];               // in-degree (edges only)
__device__ int   g_incl[NN];              // inclusive scan of g_cnt
__device__ int   g_cursor[NN];            // fill cursors (exclusive offsets)
__device__ int   g_bsum[SCAN_NB];
__device__ int   g_boff[SCAN_NB];
__device__ int   g_srcs[EE];              // CSR-by-target: source node ids
__device__ float g_coefs[EE];             // CSR-by-target: norm coefficients

// ---------------------------------------------------------------------------
// 1) init: deg = 1 (self-loop), cnt = 0
__global__ void init_kernel() {
    int i = blockIdx.x * blockDim.x + threadIdx.x;
    if (i < NN) { g_deg[i] = 1.0f; g_cnt[i] = 0; }
}

// 2) accumulate degree (float) and in-degree histogram (int) at targets
__global__ void accum_kernel(const int* __restrict__ ei,
                             const float* __restrict__ ew) {
    int e = blockIdx.x * blockDim.x + threadIdx.x;
    if (e < EE) {
        int c = ei[EE + e];
        atomicAdd(&g_deg[c], ew[e]);
        atomicAdd(&g_cnt[c], 1);
    }
}

// 3) dinv = rsqrt(deg)
__global__ void dinv_kernel() {
    int i = blockIdx.x * blockDim.x + threadIdx.x;
    if (i < NN) {
        float d = g_deg[i];
        g_dinv[i] = (d > 0.0f) ? rsqrtf(d) : 0.0f;
    }
}

// ---------------------------------------------------------------------------
// 4) scan of g_cnt (3 kernels)
__global__ void scan1_kernel() {
    __shared__ int sh[SCAN_THREADS];
    int tid  = threadIdx.x;
    int base = blockIdx.x * SCAN_CHUNK + tid * SCAN_PER_THREAD;
    int v[SCAN_PER_THREAD];
    int sum = 0;
#pragma unroll
    for (int j = 0; j < SCAN_PER_THREAD; j++) {
        int idx = base + j;
        int c = (idx < NN) ? g_cnt[idx] : 0;
        sum += c;
        v[j] = sum;                     // inclusive within thread
    }
    sh[tid] = sum;
    __syncthreads();
    // Hillis-Steele inclusive scan over thread totals
    for (int off = 1; off < SCAN_THREADS; off <<= 1) {
        int t = (tid >= off) ? sh[tid - off] : 0;
        __syncthreads();
        sh[tid] += t;
        __syncthreads();
    }
    int prefix = (tid > 0) ? sh[tid - 1] : 0;
#pragma unroll
    for (int j = 0; j < SCAN_PER_THREAD; j++) {
        int idx = base + j;
        if (idx < NN) g_incl[idx] = v[j] + prefix;
    }
    if (tid == SCAN_THREADS - 1) g_bsum[blockIdx.x] = sh[SCAN_THREADS - 1];
}

__global__ void scan2_kernel() {    // exclusive scan of 49 block sums
    if (threadIdx.x == 0 && blockIdx.x == 0) {
        int run = 0;
        for (int i = 0; i < SCAN_NB; i++) { g_boff[i] = run; run += g_bsum[i]; }
    }
}

__global__ void scan3_kernel() {
    int i = blockIdx.x * blockDim.x + threadIdx.x;
    if (i < NN) {
        int incl = g_incl[i] + g_boff[i / SCAN_CHUNK];
        g_incl[i]   = incl;
        g_cursor[i] = incl - g_cnt[i];   // exclusive start
    }
}

// 5) fill CSR: (src, coef) per edge, bucketed by target
__global__ void fill_kernel(const int* __restrict__ ei,
                            const float* __restrict__ ew) {
    int e = blockIdx.x * blockDim.x + threadIdx.x;
    if (e < EE) {
        int row = ei[e];
        int col = ei[EE + e];
        float coef = g_dinv[row] * ew[e] * g_dinv[col];
        int pos = atomicAdd(&g_cursor[col], 1);
        g_srcs[pos]  = row;
        g_coefs[pos] = coef;
    }
}

// ---------------------------------------------------------------------------
// 6) SGEMM: g_xw = x @ W. 128x128 tile, 256 threads, 8x8 microtile.
//    Both operands staged in shared (x transposed), float4 LDS only.
__global__ void __launch_bounds__(256) gemm_kernel(const float* __restrict__ x,
                                                   const float* __restrict__ w) {
    extern __shared__ float smem[];
    float* xs_t = smem;                 // [128][132] transposed x tile
    float* ws   = smem + 128 * 132;     // [128][128] W

    const int tid  = threadIdx.x;
    const int base = blockIdx.x * 128;

    const float4* xg = (const float4*)x;
    const float4* wg = (const float4*)w;
    float4*       ws4 = (float4*)ws;

    // stage W: 128*32 float4, contiguous
#pragma unroll
    for (int i = 0; i < 16; i++) ws4[tid + i * 256] = wg[tid + i * 256];

    // stage x transposed: idx -> (r = idx>>5, k4 = idx&31)
#pragma unroll
    for (int i = 0; i < 16; i++) {
        int idx = tid + i * 256;
        int r   = idx >> 5;
        int k4  = idx & 31;
        float4 v = make_float4(0.f, 0.f, 0.f, 0.f);
        if (base + r < NN) v = xg[(size_t)(base + r) * 32 + k4];
        xs_t[(k4 * 4 + 0) * 132 + r] = v.x;
        xs_t[(k4 * 4 + 1) * 132 + r] = v.y;
        xs_t[(k4 * 4 + 2) * 132 + r] = v.z;
        xs_t[(k4 * 4 + 3) * 132 + r] = v.w;
    }
    __syncthreads();

    const int tr = tid >> 4;   // 0..15 -> rows tr*8..+7
    const int tc = tid & 15;   // 0..15 -> cols tc*8..+7

    float acc[8][8];
#pragma unroll
    for (int i = 0; i < 8; i++)
#pragma unroll
        for (int j = 0; j < 8; j++) acc[i][j] = 0.0f;

#pragma unroll 2
    for (int k = 0; k < 128; k++) {
        float4 xv0 = *(const float4*)&xs_t[k * 132 + tr * 8];
        float4 xv1 = *(const float4*)&xs_t[k * 132 + tr * 8 + 4];
        float4 wv0 = *(const float4*)&ws[k * 128 + tc * 8];
        float4 wv1 = *(const float4*)&ws[k * 128 + tc * 8 + 4];
        float xv[8] = {xv0.x, xv0.y, xv0.z, xv0.w, xv1.x, xv1.y, xv1.z, xv1.w};
        float wv[8] = {wv0.x, wv0.y, wv0.z, wv0.w, wv1.x, wv1.y, wv1.z, wv1.w};
#pragma unroll
        for (int i = 0; i < 8; i++)
#pragma unroll
            for (int j = 0; j < 8; j++) acc[i][j] += xv[i] * wv[j];
    }

#pragma unroll
    for (int i = 0; i < 8; i++) {
        int r = base + tr * 8 + i;
        if (r < NN) {
            float4* o = (float4*)&g_xw[(size_t)r * 128 + tc * 8];
            o[0] = make_float4(acc[i][0], acc[i][1], acc[i][2], acc[i][3]);
            o[1] = make_float4(acc[i][4], acc[i][5], acc[i][6], acc[i][7]);
        }
    }
}

// ---------------------------------------------------------------------------
// 7) gather: warp per node. out[i] = prelu(dinv^2*xw[i] + sum coef*xw[src] + b)
__global__ void __launch_bounds__(256) gather_kernel(const float* __restrict__ bias,
                                                     const float* __restrict__ prelu_a,
                                                     float* __restrict__ out) {
    int node = (blockIdx.x * blockDim.x + threadIdx.x) >> 5;
    int lane = threadIdx.x & 31;
    if (node >= NN) return;

    int end   = g_incl[node];
    int start = end - g_cnt[node];

    const float4* xw4 = (const float4*)g_xw;

    // self-loop term
    float di = g_dinv[node];
    float s  = di * di;
    float4 acc = xw4[(size_t)node * 32 + lane];
    acc.x *= s; acc.y *= s; acc.z *= s; acc.w *= s;

#pragma unroll 4
    for (int e = start; e < end; e++) {
        int   src = __ldg(&g_srcs[e]);     // warp-broadcast
        float cf  = __ldg(&g_coefs[e]);
        float4 v  = xw4[(size_t)src * 32 + lane];
        acc.x += cf * v.x; acc.y += cf * v.y;
        acc.z += cf * v.z; acc.w += cf * v.w;
    }

    float a  = __ldg(prelu_a);
    float4 b = ((const float4*)bias)[lane];
    acc.x += b.x; acc.y += b.y; acc.z += b.z; acc.w += b.w;
    acc.x = (acc.x >= 0.f) ? acc.x : a * acc.x;
    acc.y = (acc.y >= 0.f) ? acc.y : a * acc.y;
    acc.z = (acc.z >= 0.f) ? acc.z : a * acc.z;
    acc.w = (acc.w >= 0.f) ? acc.w : a * acc.w;

    ((float4*)out)[(size_t)node * 32 + lane] = acc;
}

// ---------------------------------------------------------------------------
extern "C" void kernel_launch(void* const* d_in, const int* in_sizes, int n_in,
                              void* d_out, int out_size) {
    const float* x    = (const float*)d_in[0];
    const int*   ei   = (const int*)d_in[1];     // int32 (JAX x64 disabled)
    const float* ew   = (const float*)d_in[2];
    const float* w    = (const float*)d_in[3];
    const float* bias = (const float*)d_in[4];
    const float* pa   = (const float*)d_in[5];
    float*       out  = (float*)d_out;

    (void)in_sizes; (void)n_in; (void)out_size;

    static bool attr_done = false;
    if (!attr_done) {
        cudaFuncSetAttribute(gemm_kernel,
                             cudaFuncAttributeMaxDynamicSharedMemorySize,
                             (128 * 132 + 128 * 128) * 4);
        attr_done = true;
    }

    init_kernel<<<(NN + 255) / 256, 256>>>();
    accum_kernel<<<(EE + 255) / 256, 256>>>(ei, ew);
    dinv_kernel<<<(NN + 255) / 256, 256>>>();

    scan1_kernel<<<SCAN_NB, SCAN_THREADS>>>();
    scan2_kernel<<<1, 32>>>();
    scan3_kernel<<<(NN + 255) / 256, 256>>>();
    fill_kernel<<<(EE + 255) / 256, 256>>>(ei, ew);

    gemm_kernel<<<(NN + 127) / 128, 256, (128 * 132 + 128 * 128) * 4>>>(x, w);

    gather_kernel<<<(NN * 32 + 255) / 256, 256>>>(bias, pa, out);
}

// round 5
// speedup vs baseline: 1.6406x; 1.0015x over previous
#include <cuda_runtime.h>
#include <cstdint>

#define NN 100000
#define EE 1600000
#define DD 128

#define SCAN_THREADS 256
#define SCAN_PER_THREAD 8
#define SCAN_CHUNK (SCAN_THREADS * SCAN_PER_THREAD)   // 2048
#define SCAN_NB ((NN + SCAN_CHUNK - 1) / SCAN_CHUNK)  // 49

// Scratch (no device allocation allowed -> __device__ globals)
__device__ float g_xw[(size_t)NN * DD];   // x @ W (51.2 MB)
__device__ float g_deg[NN];
__device__ float g_dinv[NN];
__device__ int   g_cnt[NN];               // in-degree (edges only)
__device__ int   g_incl[NN];              // inclusive scan of g_cnt
__device__ int   g_cursor[NN];            // fill cursors (exclusive offsets)
__device__ int   g_bsum[SCAN_NB];
__device__ int   g_boff[SCAN_NB];
__device__ int   g_srcs[EE];              // CSR-by-target: source node ids
__device__ float g_coefs[EE];             // CSR-by-target: norm coefficients

// ---------------------------------------------------------------------------
// 1) init: deg = 1 (self-loop), cnt = 0
__global__ void init_kernel() {
    int i = blockIdx.x * blockDim.x + threadIdx.x;
    if (i < NN) { g_deg[i] = 1.0f; g_cnt[i] = 0; }
}

// 2) accumulate degree (float) and in-degree histogram (int) at targets
__global__ void accum_kernel(const int* __restrict__ ei,
                             const float* __restrict__ ew) {
    int e = blockIdx.x * blockDim.x + threadIdx.x;
    if (e < EE) {
        int c = ei[EE + e];
        atomicAdd(&g_deg[c], ew[e]);
        atomicAdd(&g_cnt[c], 1);
    }
}

// ---------------------------------------------------------------------------
// 3) scan of g_cnt (3 kernels); scan3 also computes dinv
__global__ void scan1_kernel() {
    __shared__ int sh[SCAN_THREADS];
    int tid  = threadIdx.x;
    int base = blockIdx.x * SCAN_CHUNK + tid * SCAN_PER_THREAD;
    int v[SCAN_PER_THREAD];
    int sum = 0;
#pragma unroll
    for (int j = 0; j < SCAN_PER_THREAD; j++) {
        int idx = base + j;
        int c = (idx < NN) ? g_cnt[idx] : 0;
        sum += c;
        v[j] = sum;                     // inclusive within thread
    }
    sh[tid] = sum;
    __syncthreads();
    for (int off = 1; off < SCAN_THREADS; off <<= 1) {
        int t = (tid >= off) ? sh[tid - off] : 0;
        __syncthreads();
        sh[tid] += t;
        __syncthreads();
    }
    int prefix = (tid > 0) ? sh[tid - 1] : 0;
#pragma unroll
    for (int j = 0; j < SCAN_PER_THREAD; j++) {
        int idx = base + j;
        if (idx < NN) g_incl[idx] = v[j] + prefix;
    }
    if (tid == SCAN_THREADS - 1) g_bsum[blockIdx.x] = sh[SCAN_THREADS - 1];
}

__global__ void scan2_kernel() {    // exclusive scan of 49 block sums
    if (threadIdx.x == 0 && blockIdx.x == 0) {
        int run = 0;
        for (int i = 0; i < SCAN_NB; i++) { g_boff[i] = run; run += g_bsum[i]; }
    }
}

__global__ void scan3_kernel() {    // finalize offsets + dinv
    int i = blockIdx.x * blockDim.x + threadIdx.x;
    if (i < NN) {
        int incl = g_incl[i] + g_boff[i / SCAN_CHUNK];
        g_incl[i]   = incl;
        g_cursor[i] = incl - g_cnt[i];   // exclusive start
        float d = g_deg[i];
        g_dinv[i] = (d > 0.0f) ? rsqrtf(d) : 0.0f;
    }
}

// 4) fill CSR: (src, coef) per edge, bucketed by target
__global__ void fill_kernel(const int* __restrict__ ei,
                            const float* __restrict__ ew) {
    int e = blockIdx.x * blockDim.x + threadIdx.x;
    if (e < EE) {
        int row = ei[e];
        int col = ei[EE + e];
        float coef = g_dinv[row] * ew[e] * g_dinv[col];
        int pos = atomicAdd(&g_cursor[col], 1);
        g_srcs[pos]  = row;
        g_coefs[pos] = coef;
    }
}

// ---------------------------------------------------------------------------
// 5) SGEMM: g_xw = x @ W. 128x128 tile, 256 threads, 8x8 microtile computed
//    as 8x4 packed f32x2 lanes via fma.rn.f32x2 (2x fp32 FMA throughput:
//    3-reg FFMA is half-rate on sm_103a, FFMA2 restores full rate).
__global__ void __launch_bounds__(256) gemm_kernel(const float* __restrict__ x,
                                                   const float* __restrict__ w) {
    extern __shared__ float smem[];
    float* xs_t = smem;                 // [128 k][132 r] transposed x tile
    float* ws   = smem + 128 * 132;     // [128 k][128 n] W

    const int tid  = threadIdx.x;
    const int base = blockIdx.x * 128;

    const float4* xg  = (const float4*)x;
    const float4* wg  = (const float4*)w;
    float4*       ws4 = (float4*)ws;

    // stage W: 128*32 float4, contiguous
#pragma unroll
    for (int i = 0; i < 16; i++) ws4[tid + i * 256] = wg[tid + i * 256];

    // stage x transposed: idx -> (r = idx>>5, k4 = idx&31)
#pragma unroll
    for (int i = 0; i < 16; i++) {
        int idx = tid + i * 256;
        int r   = idx >> 5;
        int k4  = idx & 31;
        float4 v = make_float4(0.f, 0.f, 0.f, 0.f);
        if (base + r < NN) v = xg[(size_t)(base + r) * 32 + k4];
        xs_t[(k4 * 4 + 0) * 132 + r] = v.x;
        xs_t[(k4 * 4 + 1) * 132 + r] = v.y;
        xs_t[(k4 * 4 + 2) * 132 + r] = v.z;
        xs_t[(k4 * 4 + 3) * 132 + r] = v.w;
    }
    __syncthreads();

    const int tr = tid >> 4;   // 0..15 -> rows tr*8..+7
    const int tc = tid & 15;   // 0..15 -> cols tc*8..+7

    // packed accumulators: acc[i][j] = cols (2j, 2j+1) of row i (fp32 pair)
    unsigned long long acc[8][4];
#pragma unroll
    for (int i = 0; i < 8; i++)
#pragma unroll
        for (int j = 0; j < 4; j++) acc[i][j] = 0ULL;

#pragma unroll 2
    for (int k = 0; k < 128; k++) {
        float4 xv0 = *(const float4*)&xs_t[k * 132 + tr * 8];
        float4 xv1 = *(const float4*)&xs_t[k * 132 + tr * 8 + 4];
        const unsigned long long* wrow =
            (const unsigned long long*)&ws[k * 128 + tc * 8];
        unsigned long long wd0 = wrow[0], wd1 = wrow[1],
                           wd2 = wrow[2], wd3 = wrow[3];
        float xv[8] = {xv0.x, xv0.y, xv0.z, xv0.w, xv1.x, xv1.y, xv1.z, xv1.w};
#pragma unroll
        for (int i = 0; i < 8; i++) {
            unsigned long long xd;
            asm("mov.b64 %0, {%1, %1};" : "=l"(xd) : "f"(xv[i]));
            asm("fma.rn.f32x2 %0, %1, %2, %0;" : "+l"(acc[i][0]) : "l"(xd), "l"(wd0));
            asm("fma.rn.f32x2 %0, %1, %2, %0;" : "+l"(acc[i][1]) : "l"(xd), "l"(wd1));
            asm("fma.rn.f32x2 %0, %1, %2, %0;" : "+l"(acc[i][2]) : "l"(xd), "l"(wd2));
            asm("fma.rn.f32x2 %0, %1, %2, %0;" : "+l"(acc[i][3]) : "l"(xd), "l"(wd3));
        }
    }

#pragma unroll
    for (int i = 0; i < 8; i++) {
        int r = base + tr * 8 + i;
        if (r < NN) {
            unsigned long long* o =
                (unsigned long long*)&g_xw[(size_t)r * 128 + tc * 8];
            o[0] = acc[i][0]; o[1] = acc[i][1];
            o[2] = acc[i][2]; o[3] = acc[i][3];
        }
    }
}

// ---------------------------------------------------------------------------
// 6) gather: warp per node, two edges in flight.
//    out[i] = prelu(dinv^2*xw[i] + sum coef*xw[src] + b)
__global__ void __launch_bounds__(256) gather_kernel(const float* __restrict__ bias,
                                                     const float* __restrict__ prelu_a,
                                                     float* __restrict__ out) {
    int node = (blockIdx.x * blockDim.x + threadIdx.x) >> 5;
    int lane = threadIdx.x & 31;
    if (node >= NN) return;

    int end   = g_incl[node];
    int start = end - g_cnt[node];

    const float4* xw4 = (const float4*)g_xw;

    // self-loop term
    float di = g_dinv[node];
    float s  = di * di;
    float4 acc0 = xw4[(size_t)node * 32 + lane];
    acc0.x *= s; acc0.y *= s; acc0.z *= s; acc0.w *= s;
    float4 acc1 = make_float4(0.f, 0.f, 0.f, 0.f);

    int e = start;
#pragma unroll 2
    for (; e + 2 <= end; e += 2) {
        int   s0 = __ldg(&g_srcs[e]);
        int   s1 = __ldg(&g_srcs[e + 1]);
        float c0 = __ldg(&g_coefs[e]);
        float c1 = __ldg(&g_coefs[e + 1]);
        float4 v0 = xw4[(size_t)s0 * 32 + lane];
        float4 v1 = xw4[(size_t)s1 * 32 + lane];
        acc0.x += c0 * v0.x; acc0.y += c0 * v0.y;
        acc0.z += c0 * v0.z; acc0.w += c0 * v0.w;
        acc1.x += c1 * v1.x; acc1.y += c1 * v1.y;
        acc1.z += c1 * v1.z; acc1.w += c1 * v1.w;
    }
    if (e < end) {
        int   s0 = __ldg(&g_srcs[e]);
        float c0 = __ldg(&g_coefs[e]);
        float4 v0 = xw4[(size_t)s0 * 32 + lane];
        acc0.x += c0 * v0.x; acc0.y += c0 * v0.y;
        acc0.z += c0 * v0.z; acc0.w += c0 * v0.w;
    }

    float a  = __ldg(prelu_a);
    float4 b = ((const float4*)bias)[lane];
    acc0.x += acc1.x + b.x; acc0.y += acc1.y + b.y;
    acc0.z += acc1.z + b.z; acc0.w += acc1.w + b.w;
    acc0.x = (acc0.x >= 0.f) ? acc0.x : a * acc0.x;
    acc0.y = (acc0.y >= 0.f) ? acc0.y : a * acc0.y;
    acc0.z = (acc0.z >= 0.f) ? acc0.z : a * acc0.z;
    acc0.w = (acc0.w >= 0.f) ? acc0.w : a * acc0.w;

    ((float4*)out)[(size_t)node * 32 + lane] = acc0;
}

// ---------------------------------------------------------------------------
extern "C" void kernel_launch(void* const* d_in, const int* in_sizes, int n_in,
                              void* d_out, int out_size) {
    const float* x    = (const float*)d_in[0];
    const int*   ei   = (const int*)d_in[1];     // int32 (JAX x64 disabled)
    const float* ew   = (const float*)d_in[2];
    const float* w    = (const float*)d_in[3];
    const float* bias = (const float*)d_in[4];
    const float* pa   = (const float*)d_in[5];
    float*       out  = (float*)d_out;

    (void)in_sizes; (void)n_in; (void)out_size;

    static bool attr_done = false;
    if (!attr_done) {
        cudaFuncSetAttribute(gemm_kernel,
                             cudaFuncAttributeMaxDynamicSharedMemorySize,
                             (128 * 132 + 128 * 128) * 4);
        attr_done = true;
    }

    init_kernel<<<(NN + 255) / 256, 256>>>();
    accum_kernel<<<(EE + 255) / 256, 256>>>(ei, ew);

    scan1_kernel<<<SCAN_NB, SCAN_THREADS>>>();
    scan2_kernel<<<1, 32>>>();
    scan3_kernel<<<(NN + 255) / 256, 256>>>();
    fill_kernel<<<(EE + 255) / 256, 256>>>(ei, ew);

    gemm_kernel<<<(NN + 127) / 128, 256, (128 * 132 + 128 * 128) * 4>>>(x, w);

    gather_kernel<<<(NN * 32 + 255) / 256, 256>>>(bias, pa, out);
}

// round 8
// speedup vs baseline: 1.7512x; 1.0674x over previous
#include <cuda_runtime.h>
#include <cstdint>

#define NN 100000
#define EE 1600000
#define DD 128

#define SCAN_THREADS 256
#define SCAN_PER_THREAD 8
#define SCAN_CHUNK (SCAN_THREADS * SCAN_PER_THREAD)   // 2048
#define SCAN_NB ((NN + SCAN_CHUNK - 1) / SCAN_CHUNK)  // 49

#define GEMM_SMEM_BYTES ((128 * 132 + 128 * 128) * 4)

// Scratch (no device allocation allowed -> __device__ globals)
__device__ float g_xw[(size_t)NN * DD];   // x @ W (51.2 MB)
__device__ float g_deg[NN];
__device__ float g_dinv[NN];
__device__ int   g_cnt[NN];               // in-degree (edges only)
__device__ int   g_incl[NN];              // inclusive scan of g_cnt
__device__ int   g_cursor[NN];            // fill cursors (exclusive offsets)
__device__ int   g_bsum[SCAN_NB];
__device__ int   g_boff[SCAN_NB];
__device__ int   g_srcs[EE];              // CSR-by-target: source node ids
__device__ float g_coefs[EE];             // CSR-by-target: norm coefficients

// ---------------------------------------------------------------------------
// 1) init: deg = 1 (self-loop), cnt = 0
__global__ void init_kernel() {
    int i = blockIdx.x * blockDim.x + threadIdx.x;
    if (i < NN) { g_deg[i] = 1.0f; g_cnt[i] = 0; }
}

// 2) accumulate degree (float) and in-degree histogram (int) at targets
__global__ void accum_kernel(const int* __restrict__ ei,
                             const float* __restrict__ ew) {
    int e = blockIdx.x * blockDim.x + threadIdx.x;
    if (e < EE) {
        int c = ei[EE + e];
        atomicAdd(&g_deg[c], ew[e]);
        atomicAdd(&g_cnt[c], 1);
    }
}

// ---------------------------------------------------------------------------
// 3) scan of g_cnt
__global__ void scan1_kernel() {
    __shared__ int sh[SCAN_THREADS];
    int tid  = threadIdx.x;
    int base = blockIdx.x * SCAN_CHUNK + tid * SCAN_PER_THREAD;
    int v[SCAN_PER_THREAD];
    int sum = 0;
#pragma unroll
    for (int j = 0; j < SCAN_PER_THREAD; j++) {
        int idx = base + j;
        int c = (idx < NN) ? g_cnt[idx] : 0;
        sum += c;
        v[j] = sum;                     // inclusive within thread
    }
    sh[tid] = sum;
    __syncthreads();
    for (int off = 1; off < SCAN_THREADS; off <<= 1) {
        int t = (tid >= off) ? sh[tid - off] : 0;
        __syncthreads();
        sh[tid] += t;
        __syncthreads();
    }
    int prefix = (tid > 0) ? sh[tid - 1] : 0;
#pragma unroll
    for (int j = 0; j < SCAN_PER_THREAD; j++) {
        int idx = base + j;
        if (idx < NN) g_incl[idx] = v[j] + prefix;
    }
    if (tid == SCAN_THREADS - 1) g_bsum[blockIdx.x] = sh[SCAN_THREADS - 1];
}

__global__ void scan2_kernel() {    // parallel exclusive scan of 49 block sums
    __shared__ int sh[64];
    int tid = threadIdx.x;
    int v = (tid < SCAN_NB) ? g_bsum[tid] : 0;
    sh[tid] = v;
    __syncthreads();
    for (int off = 1; off < 64; off <<= 1) {
        int t = (tid >= off) ? sh[tid - off] : 0;
        __syncthreads();
        sh[tid] += t;
        __syncthreads();
    }
    if (tid < SCAN_NB) g_boff[tid] = sh[tid] - v;   // exclusive
}

__global__ void scan3_kernel() {    // finalize offsets + dinv
    int i = blockIdx.x * blockDim.x + threadIdx.x;
    if (i < NN) {
        int incl = g_incl[i] + g_boff[i / SCAN_CHUNK];
        g_incl[i]   = incl;
        g_cursor[i] = incl - g_cnt[i];   // exclusive start
        float d = g_deg[i];
        g_dinv[i] = (d > 0.0f) ? rsqrtf(d) : 0.0f;
    }
}

// 4) fill CSR: (src, coef) per edge, bucketed by target
__global__ void fill_kernel(const int* __restrict__ ei,
                            const float* __restrict__ ew) {
    int e = blockIdx.x * blockDim.x + threadIdx.x;
    if (e < EE) {
        int row = ei[e];
        int col = ei[EE + e];
        float coef = g_dinv[row] * ew[e] * g_dinv[col];
        int pos = atomicAdd(&g_cursor[col], 1);
        g_srcs[pos]  = row;
        g_coefs[pos] = coef;
    }
}

// ---------------------------------------------------------------------------
// 5) SGEMM: g_xw = x @ W. 128x128 tile, 256 threads, 8x8 microtile as
//    packed fma.rn.f32x2 (FFMA2). Runs on a forked stream, overlapped with
//    the CSR-build chain.
__global__ void __launch_bounds__(256) gemm_kernel(const float* __restrict__ x,
                                                   const float* __restrict__ w) {
    extern __shared__ float smem[];
    float* xs_t = smem;                 // [128 k][132 r] transposed x tile
    float* ws   = smem + 128 * 132;     // [128 k][128 n] W

    const int tid  = threadIdx.x;
    const int base = blockIdx.x * 128;

    const float4* xg  = (const float4*)x;
    const float4* wg  = (const float4*)w;
    float4*       ws4 = (float4*)ws;

#pragma unroll
    for (int i = 0; i < 16; i++) ws4[tid + i * 256] = wg[tid + i * 256];

#pragma unroll
    for (int i = 0; i < 16; i++) {
        int idx = tid + i * 256;
        int r   = idx >> 5;
        int k4  = idx & 31;
        float4 v = make_float4(0.f, 0.f, 0.f, 0.f);
        if (base + r < NN) v = xg[(size_t)(base + r) * 32 + k4];
        xs_t[(k4 * 4 + 0) * 132 + r] = v.x;
        xs_t[(k4 * 4 + 1) * 132 + r] = v.y;
        xs_t[(k4 * 4 + 2) * 132 + r] = v.z;
        xs_t[(k4 * 4 + 3) * 132 + r] = v.w;
    }
    __syncthreads();

    const int tr = tid >> 4;
    const int tc = tid & 15;

    unsigned long long acc[8][4];
#pragma unroll
    for (int i = 0; i < 8; i++)
#pragma unroll
        for (int j = 0; j < 4; j++) acc[i][j] = 0ULL;

#pragma unroll 2
    for (int k = 0; k < 128; k++) {
        float4 xv0 = *(const float4*)&xs_t[k * 132 + tr * 8];
        float4 xv1 = *(const float4*)&xs_t[k * 132 + tr * 8 + 4];
        const unsigned long long* wrow =
            (const unsigned long long*)&ws[k * 128 + tc * 8];
        unsigned long long wd0 = wrow[0], wd1 = wrow[1],
                           wd2 = wrow[2], wd3 = wrow[3];
        float xv[8] = {xv0.x, xv0.y, xv0.z, xv0.w, xv1.x, xv1.y, xv1.z, xv1.w};
#pragma unroll
        for (int i = 0; i < 8; i++) {
            unsigned long long xd;
            asm("mov.b64 %0, {%1, %1};" : "=l"(xd) : "f"(xv[i]));
            asm("fma.rn.f32x2 %0, %1, %2, %0;" : "+l"(acc[i][0]) : "l"(xd), "l"(wd0));
            asm("fma.rn.f32x2 %0, %1, %2, %0;" : "+l"(acc[i][1]) : "l"(xd), "l"(wd1));
            asm("fma.rn.f32x2 %0, %1, %2, %0;" : "+l"(acc[i][2]) : "l"(xd), "l"(wd2));
            asm("fma.rn.f32x2 %0, %1, %2, %0;" : "+l"(acc[i][3]) : "l"(xd), "l"(wd3));
        }
    }

#pragma unroll
    for (int i = 0; i < 8; i++) {
        int r = base + tr * 8 + i;
        if (r < NN) {
            unsigned long long* o =
                (unsigned long long*)&g_xw[(size_t)r * 128 + tc * 8];
            o[0] = acc[i][0]; o[1] = acc[i][1];
            o[2] = acc[i][2]; o[3] = acc[i][3];
        }
    }
}

// ---------------------------------------------------------------------------
// 6) gather: warp per node, 4 edges in flight (2 accumulators).
__global__ void __launch_bounds__(256) gather_kernel(const float* __restrict__ bias,
                                                     const float* __restrict__ prelu_a,
                                                     float* __restrict__ out) {
    int node = (blockIdx.x * blockDim.x + threadIdx.x) >> 5;
    int lane = threadIdx.x & 31;
    if (node >= NN) return;

    int end   = g_incl[node];
    int start = end - g_cnt[node];

    const float4* xw4 = (const float4*)g_xw;

    float di = g_dinv[node];
    float s  = di * di;
    float4 acc0 = xw4[(size_t)node * 32 + lane];
    acc0.x *= s; acc0.y *= s; acc0.z *= s; acc0.w *= s;
    float4 acc1 = make_float4(0.f, 0.f, 0.f, 0.f);

    int e = start;
    for (; e + 4 <= end; e += 4) {
        int   s0 = __ldg(&g_srcs[e]);
        int   s1 = __ldg(&g_srcs[e + 1]);
        int   s2 = __ldg(&g_srcs[e + 2]);
        int   s3 = __ldg(&g_srcs[e + 3]);
        float c0 = __ldg(&g_coefs[e]);
        float c1 = __ldg(&g_coefs[e + 1]);
        float c2 = __ldg(&g_coefs[e + 2]);
        float c3 = __ldg(&g_coefs[e + 3]);
        float4 v0 = xw4[(size_t)s0 * 32 + lane];
        float4 v1 = xw4[(size_t)s1 * 32 + lane];
        float4 v2 = xw4[(size_t)s2 * 32 + lane];
        float4 v3 = xw4[(size_t)s3 * 32 + lane];
        acc0.x += c0 * v0.x; acc0.y += c0 * v0.y;
        acc0.z += c0 * v0.z; acc0.w += c0 * v0.w;
        acc1.x += c1 * v1.x; acc1.y += c1 * v1.y;
        acc1.z += c1 * v1.z; acc1.w += c1 * v1.w;
        acc0.x += c2 * v2.x; acc0.y += c2 * v2.y;
        acc0.z += c2 * v2.z; acc0.w += c2 * v2.w;
        acc1.x += c3 * v3.x; acc1.y += c3 * v3.y;
        acc1.z += c3 * v3.z; acc1.w += c3 * v3.w;
    }
    for (; e < end; e++) {
        int   s0 = __ldg(&g_srcs[e]);
        float c0 = __ldg(&g_coefs[e]);
        float4 v0 = xw4[(size_t)s0 * 32 + lane];
        acc0.x += c0 * v0.x; acc0.y += c0 * v0.y;
        acc0.z += c0 * v0.z; acc0.w += c0 * v0.w;
    }

    float a  = __ldg(prelu_a);
    float4 b = ((const float4*)bias)[lane];
    acc0.x += acc1.x + b.x; acc0.y += acc1.y + b.y;
    acc0.z += acc1.z + b.z; acc0.w += acc1.w + b.w;
    acc0.x = (acc0.x >= 0.f) ? acc0.x : a * acc0.x;
    acc0.y = (acc0.y >= 0.f) ? acc0.y : a * acc0.y;
    acc0.z = (acc0.z >= 0.f) ? acc0.z : a * acc0.z;
    acc0.w = (acc0.w >= 0.f) ? acc0.w : a * acc0.w;

    ((float4*)out)[(size_t)node * 32 + lane] = acc0;
}

// ---------------------------------------------------------------------------
// Stream/event resources: created lazily on the FIRST kernel_launch call
// (the harness's uncaptured correctness run), never inside graph capture.
// Streams/events are not device-memory allocations.
static cudaStream_t g_sB = nullptr;
static cudaEvent_t  g_evFork = nullptr, g_evJoin = nullptr;

extern "C" void kernel_launch(void* const* d_in, const int* in_sizes, int n_in,
                              void* d_out, int out_size) {
    const float* x    = (const float*)d_in[0];
    const int*   ei   = (const int*)d_in[1];     // int32 (JAX x64 disabled)
    const float* ew   = (const float*)d_in[2];
    const float* w    = (const float*)d_in[3];
    const float* bias = (const float*)d_in[4];
    const float* pa   = (const float*)d_in[5];
    float*       out  = (float*)d_out;

    (void)in_sizes; (void)n_in; (void)out_size;

    if (g_sB == nullptr) {
        cudaStreamCreateWithFlags(&g_sB, cudaStreamNonBlocking);
        cudaEventCreateWithFlags(&g_evFork, cudaEventDisableTiming);
        cudaEventCreateWithFlags(&g_evJoin, cudaEventDisableTiming);
        cudaFuncSetAttribute(gemm_kernel,
                             cudaFuncAttributeMaxDynamicSharedMemorySize,
                             GEMM_SMEM_BYTES);
    }

    // Fork: GEMM on side stream, overlapped with CSR build on main stream.
    cudaEventRecord(g_evFork, 0);
    cudaStreamWaitEvent(g_sB, g_evFork, 0);
    gemm_kernel<<<(NN + 127) / 128, 256, GEMM_SMEM_BYTES, g_sB>>>(x, w);
    cudaEventRecord(g_evJoin, g_sB);

    // CSR build chain on main stream.
    init_kernel<<<(NN + 255) / 256, 256>>>();
    accum_kernel<<<(EE + 255) / 256, 256>>>(ei, ew);
    scan1_kernel<<<SCAN_NB, SCAN_THREADS>>>();
    scan2_kernel<<<1, 64>>>();
    scan3_kernel<<<(NN + 255) / 256, 256>>>();
    fill_kernel<<<(EE + 255) / 256, 256>>>(ei, ew);

    // Join: gather needs both branches.
    cudaStreamWaitEvent(0, g_evJoin, 0);
    gather_kernel<<<(NN * 32 + 255) / 256, 256>>>(bias, pa, out);
}

// round 9
// speedup vs baseline: 2.3308x; 1.3310x over previous
#include <cuda_runtime.h>
#include <cstdint>

#define NN 100000
#define EE 1600000
#define DD 128

#define SCAN_THREADS 256
#define SCAN_PER_THREAD 8
#define SCAN_CHUNK (SCAN_THREADS * SCAN_PER_THREAD)   // 2048
#define SCAN_NB ((NN + SCAN_CHUNK - 1) / SCAN_CHUNK)  // 49

// xs[128][132] + ws[128][132] floats
#define GEMM_SMEM_BYTES ((128 * 132 + 128 * 132) * 4)

// Scratch (no device allocation allowed -> __device__ globals)
__device__ float g_xw[(size_t)NN * DD];   // x @ W (51.2 MB)
__device__ float g_deg[NN];
__device__ float g_dinv[NN];
__device__ int   g_cnt[NN];
__device__ int   g_incl[NN];
__device__ int   g_cursor[NN];
__device__ int   g_bsum[SCAN_NB];
__device__ int   g_boff[SCAN_NB];
__device__ int   g_srcs[EE];
__device__ float g_coefs[EE];

// ---------------------------------------------------------------------------
__global__ void init_kernel() {
    int i = blockIdx.x * blockDim.x + threadIdx.x;
    if (i < NN) { g_deg[i] = 1.0f; g_cnt[i] = 0; }
}

__global__ void accum_kernel(const int* __restrict__ ei,
                             const float* __restrict__ ew) {
    int e = blockIdx.x * blockDim.x + threadIdx.x;
    if (e < EE) {
        int c = ei[EE + e];
        atomicAdd(&g_deg[c], ew[e]);
        atomicAdd(&g_cnt[c], 1);
    }
}

// ---------------------------------------------------------------------------
__global__ void scan1_kernel() {
    __shared__ int sh[SCAN_THREADS];
    int tid  = threadIdx.x;
    int base = blockIdx.x * SCAN_CHUNK + tid * SCAN_PER_THREAD;
    int v[SCAN_PER_THREAD];
    int sum = 0;
#pragma unroll
    for (int j = 0; j < SCAN_PER_THREAD; j++) {
        int idx = base + j;
        int c = (idx < NN) ? g_cnt[idx] : 0;
        sum += c;
        v[j] = sum;
    }
    sh[tid] = sum;
    __syncthreads();
    for (int off = 1; off < SCAN_THREADS; off <<= 1) {
        int t = (tid >= off) ? sh[tid - off] : 0;
        __syncthreads();
        sh[tid] += t;
        __syncthreads();
    }
    int prefix = (tid > 0) ? sh[tid - 1] : 0;
#pragma unroll
    for (int j = 0; j < SCAN_PER_THREAD; j++) {
        int idx = base + j;
        if (idx < NN) g_incl[idx] = v[j] + prefix;
    }
    if (tid == SCAN_THREADS - 1) g_bsum[blockIdx.x] = sh[SCAN_THREADS - 1];
}

__global__ void scan2_kernel() {
    __shared__ int sh[64];
    int tid = threadIdx.x;
    int v = (tid < SCAN_NB) ? g_bsum[tid] : 0;
    sh[tid] = v;
    __syncthreads();
    for (int off = 1; off < 64; off <<= 1) {
        int t = (tid >= off) ? sh[tid - off] : 0;
        __syncthreads();
        sh[tid] += t;
        __syncthreads();
    }
    if (tid < SCAN_NB) g_boff[tid] = sh[tid] - v;
}

__global__ void scan3_kernel() {
    int i = blockIdx.x * blockDim.x + threadIdx.x;
    if (i < NN) {
        int incl = g_incl[i] + g_boff[i / SCAN_CHUNK];
        g_incl[i]   = incl;
        g_cursor[i] = incl - g_cnt[i];
        float d = g_deg[i];
        g_dinv[i] = (d > 0.0f) ? rsqrtf(d) : 0.0f;
    }
}

__global__ void fill_kernel(const int* __restrict__ ei,
                            const float* __restrict__ ew) {
    int e = blockIdx.x * blockDim.x + threadIdx.x;
    if (e < EE) {
        int row = ei[e];
        int col = ei[EE + e];
        float coef = g_dinv[row] * ew[e] * g_dinv[col];
        int pos = atomicAdd(&g_cursor[col], 1);
        g_srcs[pos]  = row;
        g_coefs[pos] = coef;
    }
}

// ---------------------------------------------------------------------------
// tf32 tensor-core GEMM: g_xw = x @ W.
// 128x128 tile per CTA, 8 warps, each warp: 16 rows x 128 cols via
// mma.sync.aligned.m16n8k8.row.col.f32.tf32.tf32.f32.
__device__ __forceinline__ uint32_t f2tf32(float v) {
    uint32_t r;
    asm("cvt.rna.tf32.f32 %0, %1;" : "=r"(r) : "f"(v));
    return r;
}

__global__ void __launch_bounds__(256) gemm_kernel(const float* __restrict__ x,
                                                   const float* __restrict__ w) {
    extern __shared__ float smem[];
    float* xs = smem;               // [128 r][132 k] x tile (tf32 bits)
    float* ws = smem + 128 * 132;   // [128 k][132 n] W      (tf32 bits)

    const int tid  = threadIdx.x;
    const int base = blockIdx.x * 128;

    const float4* xg  = (const float4*)x;
    const float4* wg  = (const float4*)w;

    // stage W (convert to tf32 bits): idx -> k = idx>>5, n4 = idx&31
#pragma unroll
    for (int i = 0; i < 16; i++) {
        int idx = tid + i * 256;
        int k   = idx >> 5;
        int n4  = idx & 31;
        float4 v = wg[idx];
        float4 t;
        t.x = __uint_as_float(f2tf32(v.x));
        t.y = __uint_as_float(f2tf32(v.y));
        t.z = __uint_as_float(f2tf32(v.z));
        t.w = __uint_as_float(f2tf32(v.w));
        ((float4*)ws)[k * 33 + n4] = t;
    }
    // stage x (row-major, padded): idx -> r = idx>>5, k4 = idx&31
#pragma unroll
    for (int i = 0; i < 16; i++) {
        int idx = tid + i * 256;
        int r   = idx >> 5;
        int k4  = idx & 31;
        float4 v = make_float4(0.f, 0.f, 0.f, 0.f);
        if (base + r < NN) v = xg[(size_t)(base + r) * 32 + k4];
        float4 t;
        t.x = __uint_as_float(f2tf32(v.x));
        t.y = __uint_as_float(f2tf32(v.y));
        t.z = __uint_as_float(f2tf32(v.z));
        t.w = __uint_as_float(f2tf32(v.w));
        ((float4*)xs)[r * 33 + k4] = t;
    }
    __syncthreads();

    const int warp = tid >> 5;
    const int lane = tid & 31;
    const int wrow = warp * 16;       // this warp's 16 rows
    const int grp  = lane >> 2;       // 0..7
    const int thr  = lane & 3;        // 0..3

    float c[16][4];
#pragma unroll
    for (int nt = 0; nt < 16; nt++)
#pragma unroll
        for (int j = 0; j < 4; j++) c[nt][j] = 0.0f;

#pragma unroll
    for (int kt = 0; kt < 16; kt++) {
        int k0 = kt * 8;
        // A fragment (16x8 row-major): conflict-free (banks 4*grp+thr)
        uint32_t a0 = __float_as_uint(xs[(wrow + grp)     * 132 + k0 + thr]);
        uint32_t a1 = __float_as_uint(xs[(wrow + grp + 8) * 132 + k0 + thr]);
        uint32_t a2 = __float_as_uint(xs[(wrow + grp)     * 132 + k0 + thr + 4]);
        uint32_t a3 = __float_as_uint(xs[(wrow + grp + 8) * 132 + k0 + thr + 4]);
#pragma unroll
        for (int nt = 0; nt < 16; nt++) {
            int n = nt * 8 + grp;
            // B fragment (8x8 col): conflict-free (banks 4*thr+grp)
            uint32_t b0 = __float_as_uint(ws[(k0 + thr)     * 132 + n]);
            uint32_t b1 = __float_as_uint(ws[(k0 + thr + 4) * 132 + n]);
            asm volatile(
                "mma.sync.aligned.m16n8k8.row.col.f32.tf32.tf32.f32 "
                "{%0,%1,%2,%3}, {%4,%5,%6,%7}, {%8,%9}, {%0,%1,%2,%3};"
                : "+f"(c[nt][0]), "+f"(c[nt][1]), "+f"(c[nt][2]), "+f"(c[nt][3])
                : "r"(a0), "r"(a1), "r"(a2), "r"(a3), "r"(b0), "r"(b1));
        }
    }

    // store: c0/c1 -> (row, 2*thr(+1)); c2/c3 -> (row+8, ...)
    int r0 = base + wrow + grp;
    int r1 = r0 + 8;
#pragma unroll
    for (int nt = 0; nt < 16; nt++) {
        int col = nt * 8 + 2 * thr;
        if (r0 < NN)
            *(float2*)&g_xw[(size_t)r0 * 128 + col] = make_float2(c[nt][0], c[nt][1]);
        if (r1 < NN)
            *(float2*)&g_xw[(size_t)r1 * 128 + col] = make_float2(c[nt][2], c[nt][3]);
    }
}

// ---------------------------------------------------------------------------
// gather: warp per node, 4 edges in flight (2 accumulators).
__global__ void __launch_bounds__(256) gather_kernel(const float* __restrict__ bias,
                                                     const float* __restrict__ prelu_a,
                                                     float* __restrict__ out) {
    int node = (blockIdx.x * blockDim.x + threadIdx.x) >> 5;
    int lane = threadIdx.x & 31;
    if (node >= NN) return;

    int end   = g_incl[node];
    int start = end - g_cnt[node];

    const float4* xw4 = (const float4*)g_xw;

    float di = g_dinv[node];
    float s  = di * di;
    float4 acc0 = xw4[(size_t)node * 32 + lane];
    acc0.x *= s; acc0.y *= s; acc0.z *= s; acc0.w *= s;
    float4 acc1 = make_float4(0.f, 0.f, 0.f, 0.f);

    int e = start;
    for (; e + 4 <= end; e += 4) {
        int   s0 = __ldg(&g_srcs[e]);
        int   s1 = __ldg(&g_srcs[e + 1]);
        int   s2 = __ldg(&g_srcs[e + 2]);
        int   s3 = __ldg(&g_srcs[e + 3]);
        float c0 = __ldg(&g_coefs[e]);
        float c1 = __ldg(&g_coefs[e + 1]);
        float c2 = __ldg(&g_coefs[e + 2]);
        float c3 = __ldg(&g_coefs[e + 3]);
        float4 v0 = xw4[(size_t)s0 * 32 + lane];
        float4 v1 = xw4[(size_t)s1 * 32 + lane];
        float4 v2 = xw4[(size_t)s2 * 32 + lane];
        float4 v3 = xw4[(size_t)s3 * 32 + lane];
        acc0.x += c0 * v0.x; acc0.y += c0 * v0.y;
        acc0.z += c0 * v0.z; acc0.w += c0 * v0.w;
        acc1.x += c1 * v1.x; acc1.y += c1 * v1.y;
        acc1.z += c1 * v1.z; acc1.w += c1 * v1.w;
        acc0.x += c2 * v2.x; acc0.y += c2 * v2.y;
        acc0.z += c2 * v2.z; acc0.w += c2 * v2.w;
        acc1.x += c3 * v3.x; acc1.y += c3 * v3.y;
        acc1.z += c3 * v3.z; acc1.w += c3 * v3.w;
    }
    for (; e < end; e++) {
        int   s0 = __ldg(&g_srcs[e]);
        float c0 = __ldg(&g_coefs[e]);
        float4 v0 = xw4[(size_t)s0 * 32 + lane];
        acc0.x += c0 * v0.x; acc0.y += c0 * v0.y;
        acc0.z += c0 * v0.z; acc0.w += c0 * v0.w;
    }

    float a  = __ldg(prelu_a);
    float4 b = ((const float4*)bias)[lane];
    acc0.x += acc1.x + b.x; acc0.y += acc1.y + b.y;
    acc0.z += acc1.z + b.z; acc0.w += acc1.w + b.w;
    acc0.x = (acc0.x >= 0.f) ? acc0.x : a * acc0.x;
    acc0.y = (acc0.y >= 0.f) ? acc0.y : a * acc0.y;
    acc0.z = (acc0.z >= 0.f) ? acc0.z : a * acc0.z;
    acc0.w = (acc0.w >= 0.f) ? acc0.w : a * acc0.w;

    ((float4*)out)[(size_t)node * 32 + lane] = acc0;
}

// ---------------------------------------------------------------------------
// Stream/event resources: created lazily on the FIRST kernel_launch call
// (the harness's uncaptured correctness run), never inside graph capture.
static cudaStream_t g_sB = nullptr;
static cudaEvent_t  g_evFork = nullptr, g_evJoin = nullptr;

extern "C" void kernel_launch(void* const* d_in, const int* in_sizes, int n_in,
                              void* d_out, int out_size) {
    const float* x    = (const float*)d_in[0];
    const int*   ei   = (const int*)d_in[1];     // int32 (JAX x64 disabled)
    const float* ew   = (const float*)d_in[2];
    const float* w    = (const float*)d_in[3];
    const float* bias = (const float*)d_in[4];
    const float* pa   = (const float*)d_in[5];
    float*       out  = (float*)d_out;

    (void)in_sizes; (void)n_in; (void)out_size;

    if (g_sB == nullptr) {
        cudaStreamCreateWithFlags(&g_sB, cudaStreamNonBlocking);
        cudaEventCreateWithFlags(&g_evFork, cudaEventDisableTiming);
        cudaEventCreateWithFlags(&g_evJoin, cudaEventDisableTiming);
        cudaFuncSetAttribute(gemm_kernel,
                             cudaFuncAttributeMaxDynamicSharedMemorySize,
                             GEMM_SMEM_BYTES);
    }

    // Fork: GEMM on side stream, overlapped with CSR build on main stream.
    cudaEventRecord(g_evFork, 0);
    cudaStreamWaitEvent(g_sB, g_evFork, 0);
    gemm_kernel<<<(NN + 127) / 128, 256, GEMM_SMEM_BYTES, g_sB>>>(x, w);
    cudaEventRecord(g_evJoin, g_sB);

    // CSR build chain on main stream.
    init_kernel<<<(NN + 255) / 256, 256>>>();
    accum_kernel<<<(EE + 255) / 256, 256>>>(ei, ew);
    scan1_kernel<<<SCAN_NB, SCAN_THREADS>>>();
    scan2_kernel<<<1, 64>>>();
    scan3_kernel<<<(NN + 255) / 256, 256>>>();
    fill_kernel<<<(EE + 255) / 256, 256>>>(ei, ew);

    // Join: gather needs both branches.
    cudaStreamWaitEvent(0, g_evJoin, 0);
    gather_kernel<<<(NN * 32 + 255) / 256, 256>>>(bias, pa, out);
}

// round 10
// speedup vs baseline: 2.3410x; 1.0044x over previous
#include <cuda_runtime.h>
#include <cuda_fp16.h>
#include <cstdint>

#define NN 100000
#define EE 1600000
#define DD 128

#define SCAN_THREADS 256
#define SCAN_PER_THREAD 8
#define SCAN_CHUNK (SCAN_THREADS * SCAN_PER_THREAD)   // 2048
#define SCAN_NB ((NN + SCAN_CHUNK - 1) / SCAN_CHUNK)  // 49

// xs[128][132] + ws[128][132] floats
#define GEMM_SMEM_BYTES ((128 * 132 + 128 * 132) * 4)

// Scratch (no device allocation allowed -> __device__ globals)
__device__ float  g_xw[(size_t)NN * DD];    // x @ W fp32 (51.2 MB, self term)
__device__ __half g_xwh[(size_t)NN * DD];   // x @ W fp16 (25.6 MB, messages)
__device__ float  g_deg[NN];
__device__ float  g_dinv[NN];
__device__ int    g_cnt[NN];
__device__ int    g_incl[NN];
__device__ int    g_cursor[NN];
__device__ int    g_bsum[SCAN_NB];
__device__ int    g_boff[SCAN_NB];
__device__ int2   g_epack[EE];              // CSR-by-target: (src, coef bits)

// ---------------------------------------------------------------------------
__global__ void init_kernel() {
    int i = blockIdx.x * blockDim.x + threadIdx.x;
    if (i < NN) { g_deg[i] = 1.0f; g_cnt[i] = 0; }
}

__global__ void accum_kernel(const int* __restrict__ ei,
                             const float* __restrict__ ew) {
    int e = blockIdx.x * blockDim.x + threadIdx.x;
    if (e < EE) {
        int c = ei[EE + e];
        atomicAdd(&g_deg[c], ew[e]);
        atomicAdd(&g_cnt[c], 1);
    }
}

// ---------------------------------------------------------------------------
__global__ void scan1_kernel() {
    __shared__ int sh[SCAN_THREADS];
    int tid  = threadIdx.x;
    int base = blockIdx.x * SCAN_CHUNK + tid * SCAN_PER_THREAD;
    int v[SCAN_PER_THREAD];
    int sum = 0;
#pragma unroll
    for (int j = 0; j < SCAN_PER_THREAD; j++) {
        int idx = base + j;
        int c = (idx < NN) ? g_cnt[idx] : 0;
        sum += c;
        v[j] = sum;
    }
    sh[tid] = sum;
    __syncthreads();
    for (int off = 1; off < SCAN_THREADS; off <<= 1) {
        int t = (tid >= off) ? sh[tid - off] : 0;
        __syncthreads();
        sh[tid] += t;
        __syncthreads();
    }
    int prefix = (tid > 0) ? sh[tid - 1] : 0;
#pragma unroll
    for (int j = 0; j < SCAN_PER_THREAD; j++) {
        int idx = base + j;
        if (idx < NN) g_incl[idx] = v[j] + prefix;
    }
    if (tid == SCAN_THREADS - 1) g_bsum[blockIdx.x] = sh[SCAN_THREADS - 1];
}

__global__ void scan2_kernel() {
    __shared__ int sh[64];
    int tid = threadIdx.x;
    int v = (tid < SCAN_NB) ? g_bsum[tid] : 0;
    sh[tid] = v;
    __syncthreads();
    for (int off = 1; off < 64; off <<= 1) {
        int t = (tid >= off) ? sh[tid - off] : 0;
        __syncthreads();
        sh[tid] += t;
        __syncthreads();
    }
    if (tid < SCAN_NB) g_boff[tid] = sh[tid] - v;
}

__global__ void scan3_kernel() {
    int i = blockIdx.x * blockDim.x + threadIdx.x;
    if (i < NN) {
        int incl = g_incl[i] + g_boff[i / SCAN_CHUNK];
        g_incl[i]   = incl;
        g_cursor[i] = incl - g_cnt[i];
        float d = g_deg[i];
        g_dinv[i] = (d > 0.0f) ? rsqrtf(d) : 0.0f;
    }
}

__global__ void fill_kernel(const int* __restrict__ ei,
                            const float* __restrict__ ew) {
    int e = blockIdx.x * blockDim.x + threadIdx.x;
    if (e < EE) {
        int row = ei[e];
        int col = ei[EE + e];
        float coef = g_dinv[row] * ew[e] * g_dinv[col];
        int pos = atomicAdd(&g_cursor[col], 1);
        g_epack[pos] = make_int2(row, __float_as_int(coef));
    }
}

// ---------------------------------------------------------------------------
// tf32 tensor-core GEMM: g_xw (fp32) + g_xwh (fp16) = x @ W.
__device__ __forceinline__ uint32_t f2tf32(float v) {
    uint32_t r;
    asm("cvt.rna.tf32.f32 %0, %1;" : "=r"(r) : "f"(v));
    return r;
}

__global__ void __launch_bounds__(256) gemm_kernel(const float* __restrict__ x,
                                                   const float* __restrict__ w) {
    extern __shared__ float smem[];
    float* xs = smem;               // [128 r][132 k] x tile (tf32 bits)
    float* ws = smem + 128 * 132;   // [128 k][132 n] W      (tf32 bits)

    const int tid  = threadIdx.x;
    const int base = blockIdx.x * 128;

    const float4* xg  = (const float4*)x;
    const float4* wg  = (const float4*)w;

#pragma unroll
    for (int i = 0; i < 16; i++) {
        int idx = tid + i * 256;
        int k   = idx >> 5;
        int n4  = idx & 31;
        float4 v = wg[idx];
        float4 t;
        t.x = __uint_as_float(f2tf32(v.x));
        t.y = __uint_as_float(f2tf32(v.y));
        t.z = __uint_as_float(f2tf32(v.z));
        t.w = __uint_as_float(f2tf32(v.w));
        ((float4*)ws)[k * 33 + n4] = t;
    }
#pragma unroll
    for (int i = 0; i < 16; i++) {
        int idx = tid + i * 256;
        int r   = idx >> 5;
        int k4  = idx & 31;
        float4 v = make_float4(0.f, 0.f, 0.f, 0.f);
        if (base + r < NN) v = xg[(size_t)(base + r) * 32 + k4];
        float4 t;
        t.x = __uint_as_float(f2tf32(v.x));
        t.y = __uint_as_float(f2tf32(v.y));
        t.z = __uint_as_float(f2tf32(v.z));
        t.w = __uint_as_float(f2tf32(v.w));
        ((float4*)xs)[r * 33 + k4] = t;
    }
    __syncthreads();

    const int warp = tid >> 5;
    const int lane = tid & 31;
    const int wrow = warp * 16;
    const int grp  = lane >> 2;
    const int thr  = lane & 3;

    float c[16][4];
#pragma unroll
    for (int nt = 0; nt < 16; nt++)
#pragma unroll
        for (int j = 0; j < 4; j++) c[nt][j] = 0.0f;

#pragma unroll
    for (int kt = 0; kt < 16; kt++) {
        int k0 = kt * 8;
        uint32_t a0 = __float_as_uint(xs[(wrow + grp)     * 132 + k0 + thr]);
        uint32_t a1 = __float_as_uint(xs[(wrow + grp + 8) * 132 + k0 + thr]);
        uint32_t a2 = __float_as_uint(xs[(wrow + grp)     * 132 + k0 + thr + 4]);
        uint32_t a3 = __float_as_uint(xs[(wrow + grp + 8) * 132 + k0 + thr + 4]);
#pragma unroll
        for (int nt = 0; nt < 16; nt++) {
            int n = nt * 8 + grp;
            uint32_t b0 = __float_as_uint(ws[(k0 + thr)     * 132 + n]);
            uint32_t b1 = __float_as_uint(ws[(k0 + thr + 4) * 132 + n]);
            asm volatile(
                "mma.sync.aligned.m16n8k8.row.col.f32.tf32.tf32.f32 "
                "{%0,%1,%2,%3}, {%4,%5,%6,%7}, {%8,%9}, {%0,%1,%2,%3};"
                : "+f"(c[nt][0]), "+f"(c[nt][1]), "+f"(c[nt][2]), "+f"(c[nt][3])
                : "r"(a0), "r"(a1), "r"(a2), "r"(a3), "r"(b0), "r"(b1));
        }
    }

    int r0 = base + wrow + grp;
    int r1 = r0 + 8;
#pragma unroll
    for (int nt = 0; nt < 16; nt++) {
        int col = nt * 8 + 2 * thr;
        if (r0 < NN) {
            *(float2*)&g_xw[(size_t)r0 * 128 + col] = make_float2(c[nt][0], c[nt][1]);
            *(__half2*)&g_xwh[(size_t)r0 * 128 + col] =
                __floats2half2_rn(c[nt][0], c[nt][1]);
        }
        if (r1 < NN) {
            *(float2*)&g_xw[(size_t)r1 * 128 + col] = make_float2(c[nt][2], c[nt][3]);
            *(__half2*)&g_xwh[(size_t)r1 * 128 + col] =
                __floats2half2_rn(c[nt][2], c[nt][3]);
        }
    }
}

// ---------------------------------------------------------------------------
// gather: warp per node; messages from fp16 copy (half the L2 traffic),
// self term from fp32. 4 edges in flight, 2 accumulators.
__device__ __forceinline__ float4 load_h4(int src, int lane) {
    uint2 raw = *(const uint2*)(g_xwh + (size_t)src * 128 + lane * 4);
    __half2 h0 = *reinterpret_cast<const __half2*>(&raw.x);
    __half2 h1 = *reinterpret_cast<const __half2*>(&raw.y);
    float2 f0 = __half22float2(h0);
    float2 f1 = __half22float2(h1);
    return make_float4(f0.x, f0.y, f1.x, f1.y);
}

__global__ void __launch_bounds__(256) gather_kernel(const float* __restrict__ bias,
                                                     const float* __restrict__ prelu_a,
                                                     float* __restrict__ out) {
    int node = (blockIdx.x * blockDim.x + threadIdx.x) >> 5;
    int lane = threadIdx.x & 31;
    if (node >= NN) return;

    int end   = g_incl[node];
    int start = end - g_cnt[node];

    float di = g_dinv[node];
    float s  = di * di;
    float4 acc0 = ((const float4*)g_xw)[(size_t)node * 32 + lane];
    acc0.x *= s; acc0.y *= s; acc0.z *= s; acc0.w *= s;
    float4 acc1 = make_float4(0.f, 0.f, 0.f, 0.f);

    int e = start;
    for (; e + 4 <= end; e += 4) {
        int2 p0 = __ldg(&g_epack[e]);
        int2 p1 = __ldg(&g_epack[e + 1]);
        int2 p2 = __ldg(&g_epack[e + 2]);
        int2 p3 = __ldg(&g_epack[e + 3]);
        float4 v0 = load_h4(p0.x, lane);
        float4 v1 = load_h4(p1.x, lane);
        float4 v2 = load_h4(p2.x, lane);
        float4 v3 = load_h4(p3.x, lane);
        float c0 = __int_as_float(p0.y);
        float c1 = __int_as_float(p1.y);
        float c2 = __int_as_float(p2.y);
        float c3 = __int_as_float(p3.y);
        acc0.x += c0 * v0.x; acc0.y += c0 * v0.y;
        acc0.z += c0 * v0.z; acc0.w += c0 * v0.w;
        acc1.x += c1 * v1.x; acc1.y += c1 * v1.y;
        acc1.z += c1 * v1.z; acc1.w += c1 * v1.w;
        acc0.x += c2 * v2.x; acc0.y += c2 * v2.y;
        acc0.z += c2 * v2.z; acc0.w += c2 * v2.w;
        acc1.x += c3 * v3.x; acc1.y += c3 * v3.y;
        acc1.z += c3 * v3.z; acc1.w += c3 * v3.w;
    }
    for (; e < end; e++) {
        int2 p0 = __ldg(&g_epack[e]);
        float4 v0 = load_h4(p0.x, lane);
        float c0 = __int_as_float(p0.y);
        acc0.x += c0 * v0.x; acc0.y += c0 * v0.y;
        acc0.z += c0 * v0.z; acc0.w += c0 * v0.w;
    }

    float a  = __ldg(prelu_a);
    float4 b = ((const float4*)bias)[lane];
    acc0.x += acc1.x + b.x; acc0.y += acc1.y + b.y;
    acc0.z += acc1.z + b.z; acc0.w += acc1.w + b.w;
    acc0.x = (acc0.x >= 0.f) ? acc0.x : a * acc0.x;
    acc0.y = (acc0.y >= 0.f) ? acc0.y : a * acc0.y;
    acc0.z = (acc0.z >= 0.f) ? acc0.z : a * acc0.z;
    acc0.w = (acc0.w >= 0.f) ? acc0.w : a * acc0.w;

    ((float4*)out)[(size_t)node * 32 + lane] = acc0;
}

// ---------------------------------------------------------------------------
// Stream/event resources: created lazily on the FIRST kernel_launch call
// (the harness's uncaptured correctness run), never inside graph capture.
static cudaStream_t g_sB = nullptr;
static cudaEvent_t  g_evFork = nullptr, g_evJoin = nullptr;

extern "C" void kernel_launch(void* const* d_in, const int* in_sizes, int n_in,
                              void* d_out, int out_size) {
    const float* x    = (const float*)d_in[0];
    const int*   ei   = (const int*)d_in[1];     // int32 (JAX x64 disabled)
    const float* ew   = (const float*)d_in[2];
    const float* w    = (const float*)d_in[3];
    const float* bias = (const float*)d_in[4];
    const float* pa   = (const float*)d_in[5];
    float*       out  = (float*)d_out;

    (void)in_sizes; (void)n_in; (void)out_size;

    if (g_sB == nullptr) {
        cudaStreamCreateWithFlags(&g_sB, cudaStreamNonBlocking);
        cudaEventCreateWithFlags(&g_evFork, cudaEventDisableTiming);
        cudaEventCreateWithFlags(&g_evJoin, cudaEventDisableTiming);
        cudaFuncSetAttribute(gemm_kernel,
                             cudaFuncAttributeMaxDynamicSharedMemorySize,
                             GEMM_SMEM_BYTES);
    }

    // Fork: GEMM on side stream, overlapped with CSR build on main stream.
    cudaEventRecord(g_evFork, 0);
    cudaStreamWaitEvent(g_sB, g_evFork, 0);
    gemm_kernel<<<(NN + 127) / 128, 256, GEMM_SMEM_BYTES, g_sB>>>(x, w);
    cudaEventRecord(g_evJoin, g_sB);

    // CSR build chain on main stream.
    init_kernel<<<(NN + 255) / 256, 256>>>();
    accum_kernel<<<(EE + 255) / 256, 256>>>(ei, ew);
    scan1_kernel<<<SCAN_NB, SCAN_THREADS>>>();
    scan2_kernel<<<1, 64>>>();
    scan3_kernel<<<(NN + 255) / 256, 256>>>();
    fill_kernel<<<(EE + 255) / 256, 256>>>(ei, ew);

    // Join: gather needs both branches.
    cudaStreamWaitEvent(0, g_evJoin, 0);
    gather_kernel<<<(NN * 32 + 255) / 256, 256>>>(bias, pa, out);
}